// round 3
// baseline (speedup 1.0000x reference)
#include <cuda_runtime.h>
#include <cstdint>

#define NN 100000
#define NE 1600000

typedef unsigned long long ull;

// Scratch (device globals — no runtime allocation allowed)
__device__ float g_SR[(size_t)NN * 256];  // [n][0:128]=nodes@W1a+b1, [128:256]=nodes@W1b
__device__ float g_deg[NN];               // degree, then 1/max(deg,1)

// ---------------------------------------------------------------------------
// packed fp32x2 helpers
// ---------------------------------------------------------------------------
__device__ __forceinline__ ull dup2(float x) {
    ull r; asm("mov.b64 %0,{%1,%1};" : "=l"(r) : "f"(x)); return r;
}
__device__ __forceinline__ float2 up2(ull v) {
    float2 r; asm("mov.b64 {%0,%1},%2;" : "=f"(r.x), "=f"(r.y) : "l"(v)); return r;
}
__device__ __forceinline__ ull pk2(float x, float y) {
    ull r; asm("mov.b64 %0,{%1,%2};" : "=l"(r) : "f"(x), "f"(y)); return r;
}
__device__ __forceinline__ ull fma2(ull a, ull b, ull c) {
    ull d; asm("fma.rn.f32x2 %0,%1,%2,%3;" : "=l"(d) : "l"(a), "l"(b), "l"(c)); return d;
}

// ---------------------------------------------------------------------------
// Degree kernels
// ---------------------------------------------------------------------------
__global__ void zero_deg_kernel() {
    int i = blockIdx.x * blockDim.x + threadIdx.x;
    if (i < NN) g_deg[i] = 0.0f;
}
__global__ void deg_kernel(const int* __restrict__ recv) {
    int e = blockIdx.x * blockDim.x + threadIdx.x;
    if (e < NE) atomicAdd(&g_deg[recv[e]], 1.0f);
}
__global__ void invdeg_kernel() {
    int i = blockIdx.x * blockDim.x + threadIdx.x;
    if (i < NN) g_deg[i] = 1.0f / fmaxf(g_deg[i], 1.0f);
}

// ---------------------------------------------------------------------------
// Fused S|R precompute: g_SR[M,256] = nodes[M,64] @ [W1a | W1b][64,256], b1 on S half
// ---------------------------------------------------------------------------
__global__ void __launch_bounds__(256) sr_gemm_kernel(
    const float* __restrict__ A,   // nodes [M,64]
    const float* __restrict__ W1,  // [160,128]
    const float* __restrict__ b1,  // [128]
    int M)
{
    extern __shared__ float sm[];
    float* sAT = sm;               // [64 k][68] transposed A tile
    float* sB  = sm + 64 * 68;     // [64 k][256 n]

    const int tid = threadIdx.x;
    const int n0  = blockIdx.x * 64;

#pragma unroll
    for (int j = 0; j < 4; j++) {
        int s   = tid + j * 256;
        int row = s >> 4;
        int k0  = (s & 15) << 2;
        int gn  = n0 + row;
        float4 v = make_float4(0.f, 0.f, 0.f, 0.f);
        if (gn < M) v = *(const float4*)(A + (size_t)gn * 64 + k0);
        sAT[(k0 + 0) * 68 + row] = v.x;
        sAT[(k0 + 1) * 68 + row] = v.y;
        sAT[(k0 + 2) * 68 + row] = v.z;
        sAT[(k0 + 3) * 68 + row] = v.w;
    }
#pragma unroll
    for (int j = 0; j < 16; j++) {
        int s  = tid + j * 256;
        int r  = s >> 6;
        int c4 = (s & 63) * 4;
        const float* src = (c4 < 128) ? (W1 + (size_t)r * 128 + c4)
                                      : (W1 + (size_t)(64 + r) * 128 + (c4 - 128));
        *(float4*)(sB + r * 256 + c4) = *(const float4*)src;
    }
    __syncthreads();

    const int ty = tid >> 4;
    const int tx = tid & 15;

    ull acc[4][4][2];
#pragma unroll
    for (int m = 0; m < 4; m++)
#pragma unroll
        for (int q = 0; q < 4; q++) { acc[m][q][0] = 0ull; acc[m][q][1] = 0ull; }

#pragma unroll 8
    for (int k = 0; k < 64; k++) {
        float4 a = *(const float4*)(sAT + k * 68 + ty * 4);
        ull aa[4] = {dup2(a.x), dup2(a.y), dup2(a.z), dup2(a.w)};
#pragma unroll
        for (int q = 0; q < 4; q++) {
            ulonglong2 b = *(const ulonglong2*)(sB + k * 256 + q * 64 + tx * 4);
#pragma unroll
            for (int m = 0; m < 4; m++) {
                acc[m][q][0] = fma2(aa[m], b.x, acc[m][q][0]);
                acc[m][q][1] = fma2(aa[m], b.y, acc[m][q][1]);
            }
        }
    }

    float4 bq[4];
#pragma unroll
    for (int q = 0; q < 4; q++) {
        if (q < 2) bq[q] = *(const float4*)(b1 + q * 64 + tx * 4);
        else       bq[q] = make_float4(0.f, 0.f, 0.f, 0.f);
    }

#pragma unroll
    for (int m = 0; m < 4; m++) {
        int gn = n0 + ty * 4 + m;
        if (gn < M) {
#pragma unroll
            for (int q = 0; q < 4; q++) {
                float2 u0 = up2(acc[m][q][0]);
                float2 u1 = up2(acc[m][q][1]);
                float4 v = make_float4(u0.x + bq[q].x, u0.y + bq[q].y,
                                       u1.x + bq[q].z, u1.y + bq[q].w);
                *(float4*)(g_SR + (size_t)gn * 256 + q * 64 + tx * 4) = v;
            }
        }
    }
}

// ---------------------------------------------------------------------------
// Node residual GEMM: out[M,64] = nodes @ Wn + bn
// ---------------------------------------------------------------------------
__global__ void __launch_bounds__(256) node_gemm_small(
    const float* __restrict__ A, const float* __restrict__ B,
    const float* __restrict__ bias, float* __restrict__ C, int M)
{
    extern __shared__ float sm[];
    float* sAT = sm;
    float* sB  = sm + 64 * 68;

    const int tid = threadIdx.x;
    const int n0  = blockIdx.x * 64;

#pragma unroll
    for (int j = 0; j < 4; j++) {
        int s   = tid + j * 256;
        int row = s >> 4;
        int k0  = (s & 15) << 2;
        int gn  = n0 + row;
        float4 v = make_float4(0.f, 0.f, 0.f, 0.f);
        if (gn < M) v = *(const float4*)(A + (size_t)gn * 64 + k0);
        sAT[(k0 + 0) * 68 + row] = v.x;
        sAT[(k0 + 1) * 68 + row] = v.y;
        sAT[(k0 + 2) * 68 + row] = v.z;
        sAT[(k0 + 3) * 68 + row] = v.w;
    }
#pragma unroll
    for (int j = 0; j < 4; j++) {
        int s = tid + j * 256;
        ((float4*)sB)[s] = ((const float4*)B)[s];
    }
    __syncthreads();

    const int ty = tid >> 4, tx = tid & 15;
    ull acc[4][2];
#pragma unroll
    for (int m = 0; m < 4; m++) { acc[m][0] = 0ull; acc[m][1] = 0ull; }

#pragma unroll 8
    for (int k = 0; k < 64; k++) {
        float4 a = *(const float4*)(sAT + k * 68 + ty * 4);
        ulonglong2 b = *(const ulonglong2*)(sB + k * 64 + tx * 4);
        ull aa[4] = {dup2(a.x), dup2(a.y), dup2(a.z), dup2(a.w)};
#pragma unroll
        for (int m = 0; m < 4; m++) {
            acc[m][0] = fma2(aa[m], b.x, acc[m][0]);
            acc[m][1] = fma2(aa[m], b.y, acc[m][1]);
        }
    }

    float4 bb = *(const float4*)(bias + tx * 4);
#pragma unroll
    for (int m = 0; m < 4; m++) {
        int gn = n0 + ty * 4 + m;
        if (gn < M) {
            float2 u0 = up2(acc[m][0]);
            float2 u1 = up2(acc[m][1]);
            float4 v = make_float4(u0.x + bb.x, u0.y + bb.y, u1.x + bb.z, u1.y + bb.w);
            *(float4*)(C + (size_t)gn * 64 + tx * 4) = v;
        }
    }
}

// ---------------------------------------------------------------------------
// Fused edge kernel: 256 edges / block, 512 threads, k-packed f32x2 throughout
// ---------------------------------------------------------------------------
__global__ void __launch_bounds__(512) edge_kernel(
    const float* __restrict__ edges,       // [NE,32]
    const int*   __restrict__ senders,
    const int*   __restrict__ receivers,
    const float* __restrict__ W1,          // [160,128]
    const float* __restrict__ W2,          // [128,64]
    const float* __restrict__ b2,          // [64]
    float*       __restrict__ out)         // [NN,64]
{
    extern __shared__ float sm[];
    float* sW1c = sm;                      // [32][128] = 4096
    float* sW2T = sm + 4096;               // [64 n][128 k] XOR-swizzled = 8192
    float* sE   = sm + 12288;              // [256 e][36] = 9216
    float* sH   = sm + 12288 + 9216;       // [256 e][132] = 33792
    int*   sSend = (int*)(sH + 33792);     // [256]
    int*   sRecv = sSend + 256;            // [256]

    const int tid = threadIdx.x;
    const int e0  = blockIdx.x * 256;

    if (tid < 256) sSend[tid] = senders[e0 + tid];
    else           sRecv[tid - 256] = receivers[e0 + tid - 256];

    // W1 rows 128..159 -> sW1c (linear)
#pragma unroll
    for (int j = 0; j < 2; j++) {
        int s = tid + j * 512;
        ((float4*)sW1c)[s] = ((const float4*)(W1 + 128 * 128))[s];
    }
    // W2 -> sW2T[n][k] with XOR swizzle on k-pairs: foff = n*128 + 2*((k/2)^(n&7)) + (k&1)
#pragma unroll
    for (int j = 0; j < 16; j++) {
        int s = tid + j * 512;
        int k = s >> 6;
        int n = s & 63;
        sW2T[n * 128 + 2 * ((k >> 1) ^ (n & 7)) + (k & 1)] = W2[s];
    }
    // edges -> sE row-major [e][32]
#pragma unroll
    for (int j = 0; j < 4; j++) {
        int s  = tid + j * 512;
        int e  = s >> 3;
        int i0 = (s & 7) * 4;
        *(float4*)(sE + e * 36 + i0) = *(const float4*)(edges + (size_t)(e0 + e) * 32 + i0);
    }
    __syncthreads();

    // ================= GEMM1: h[256e x 128k], pack along k =================
    {
        const int ty = tid >> 4;           // 0..31 -> edges ty*8..+7
        const int tx = tid & 15;           // 0..15 -> k cols tx*8..+7
        const int eb = ty * 8;
        const int kb = tx * 8;

        ull acc[8][4];
#pragma unroll
        for (int e = 0; e < 8; e++)
#pragma unroll
            for (int c = 0; c < 4; c++) acc[e][c] = 0ull;

#pragma unroll
        for (int i0 = 0; i0 < 32; i0 += 4) {
            float4 ev[8];
#pragma unroll
            for (int e = 0; e < 8; e++)
                ev[e] = *(const float4*)(sE + (eb + e) * 36 + i0);
#pragma unroll
            for (int ii = 0; ii < 4; ii++) {
                ulonglong2 w01 = *(const ulonglong2*)(sW1c + (i0 + ii) * 128 + kb);
                ulonglong2 w23 = *(const ulonglong2*)(sW1c + (i0 + ii) * 128 + kb + 4);
#pragma unroll
                for (int e = 0; e < 8; e++) {
                    float es = (ii == 0) ? ev[e].x : (ii == 1) ? ev[e].y
                             : (ii == 2) ? ev[e].z : ev[e].w;
                    ull aa = dup2(es);
                    acc[e][0] = fma2(aa, w01.x, acc[e][0]);
                    acc[e][1] = fma2(aa, w01.y, acc[e][1]);
                    acc[e][2] = fma2(aa, w23.x, acc[e][2]);
                    acc[e][3] = fma2(aa, w23.y, acc[e][3]);
                }
            }
        }

        // epilogue: h = relu(acc + S[send] + R[recv]); store [e][k] row-major
#pragma unroll
        for (int e = 0; e < 8; e++) {
            int ge = eb + e;
            int es = sSend[ge];
            int er = sRecv[ge];
            const float* Sp = g_SR + (size_t)es * 256 + kb;
            const float* Rp = g_SR + (size_t)er * 256 + 128 + kb;
            float4 s0 = *(const float4*)(Sp);
            float4 s1 = *(const float4*)(Sp + 4);
            float4 r0 = *(const float4*)(Rp);
            float4 r1 = *(const float4*)(Rp + 4);
            float2 u;
            u = up2(acc[e][0]);
            ull p0 = pk2(fmaxf(u.x + s0.x + r0.x, 0.f), fmaxf(u.y + s0.y + r0.y, 0.f));
            u = up2(acc[e][1]);
            ull p1 = pk2(fmaxf(u.x + s0.z + r0.z, 0.f), fmaxf(u.y + s0.w + r0.w, 0.f));
            u = up2(acc[e][2]);
            ull p2 = pk2(fmaxf(u.x + s1.x + r1.x, 0.f), fmaxf(u.y + s1.y + r1.y, 0.f));
            u = up2(acc[e][3]);
            ull p3 = pk2(fmaxf(u.x + s1.z + r1.z, 0.f), fmaxf(u.y + s1.w + r1.w, 0.f));
            ulonglong2* dst = (ulonglong2*)(sH + ge * 132 + kb);
            dst[0] = make_ulonglong2(p0, p1);
            dst[1] = make_ulonglong2(p2, p3);
        }
    }
    __syncthreads();

    // ========== GEMM2: m[256e x 64n] = h @ W2, pack along k, hadd at end ==========
    {
        const int ty2 = tid >> 3;          // 0..63 -> edges ty2*4..+3
        const int tx2 = tid & 7;           // 0..7  -> n cols tx2*8..+7
        const int eb2 = ty2 * 4;
        const int nb  = tx2 * 8;

        const float* hb0 = sH + (eb2 + 0) * 132;
        const float* hb1 = sH + (eb2 + 1) * 132;
        const float* hb2 = sH + (eb2 + 2) * 132;
        const float* hb3 = sH + (eb2 + 3) * 132;
        const float* wb[8];
#pragma unroll
        for (int j = 0; j < 8; j++) wb[j] = sW2T + (nb + j) * 128;

        ull acc2[4][8];
#pragma unroll
        for (int e = 0; e < 4; e++)
#pragma unroll
            for (int j = 0; j < 8; j++) acc2[e][j] = 0ull;

#pragma unroll 2
        for (int kq = 0; kq < 8; kq++) {
            int kqo = kq * 16;
#pragma unroll
            for (int kr = 0; kr < 8; kr++) {
                ull hv0 = *(const ull*)(hb0 + kqo + kr * 2);
                ull hv1 = *(const ull*)(hb1 + kqo + kr * 2);
                ull hv2 = *(const ull*)(hb2 + kqo + kr * 2);
                ull hv3 = *(const ull*)(hb3 + kqo + kr * 2);
#pragma unroll
                for (int j = 0; j < 8; j++) {
                    ull wv = *(const ull*)(wb[j] + kqo + 2 * (kr ^ j));
                    acc2[0][j] = fma2(hv0, wv, acc2[0][j]);
                    acc2[1][j] = fma2(hv1, wv, acc2[1][j]);
                    acc2[2][j] = fma2(hv2, wv, acc2[2][j]);
                    acc2[3][j] = fma2(hv3, wv, acc2[3][j]);
                }
            }
        }

        // epilogue 2: m = hadd(acc2) + b2, scale by invdeg, vector-red scatter
        float4 b2a = *(const float4*)(b2 + nb);
        float4 b2b = *(const float4*)(b2 + nb + 4);
        float bnv[8] = {b2a.x, b2a.y, b2a.z, b2a.w, b2b.x, b2b.y, b2b.z, b2b.w};

#pragma unroll
        for (int e = 0; e < 4; e++) {
            int er = sRecv[eb2 + e];
            float invd = g_deg[er];
            float mv[8];
#pragma unroll
            for (int j = 0; j < 8; j++) {
                float2 u = up2(acc2[e][j]);
                mv[j] = (u.x + u.y + bnv[j]) * invd;
            }
            float* p = out + (size_t)er * 64 + nb;
            asm volatile("red.global.add.v4.f32 [%0], {%1,%2,%3,%4};"
                         :: "l"(p), "f"(mv[0]), "f"(mv[1]), "f"(mv[2]), "f"(mv[3]) : "memory");
            asm volatile("red.global.add.v4.f32 [%0], {%1,%2,%3,%4};"
                         :: "l"(p + 4), "f"(mv[4]), "f"(mv[5]), "f"(mv[6]), "f"(mv[7]) : "memory");
        }
    }
}

// ---------------------------------------------------------------------------
// Launch
// ---------------------------------------------------------------------------
extern "C" void kernel_launch(void* const* d_in, const int* in_sizes, int n_in,
                              void* d_out, int out_size)
{
    const float* nodes     = (const float*)d_in[0];
    const float* edges     = (const float*)d_in[1];
    const int*   senders   = (const int*)d_in[2];
    const int*   receivers = (const int*)d_in[3];
    const float* W1        = (const float*)d_in[4];
    const float* b1        = (const float*)d_in[5];
    const float* W2        = (const float*)d_in[6];
    const float* b2        = (const float*)d_in[7];
    const float* Wn        = (const float*)d_in[8];
    const float* bn        = (const float*)d_in[9];
    float* out = (float*)d_out;

    const size_t sm_sr    = (64 * 68 + 64 * 256) * sizeof(float);
    const size_t sm_small = (64 * 68 + 64 * 64) * sizeof(float);
    const size_t sm_edge  = (4096 + 8192 + 9216 + 33792) * sizeof(float) + 512 * sizeof(int);

    cudaFuncSetAttribute(sr_gemm_kernel,
                         cudaFuncAttributeMaxDynamicSharedMemorySize, (int)sm_sr);
    cudaFuncSetAttribute(edge_kernel,
                         cudaFuncAttributeMaxDynamicSharedMemorySize, (int)sm_edge);

    zero_deg_kernel<<<(NN + 255) / 256, 256>>>();
    deg_kernel<<<(NE + 255) / 256, 256>>>(receivers);
    invdeg_kernel<<<(NN + 255) / 256, 256>>>();

    int gnodes = (NN + 63) / 64;
    sr_gemm_kernel<<<gnodes, 256, sm_sr>>>(nodes, W1, b1, NN);
    node_gemm_small<<<gnodes, 256, sm_small>>>(nodes, Wn, bn, out, NN);

    edge_kernel<<<NE / 256, 512, sm_edge>>>(edges, senders, receivers, W1, W2, b2, out);
}

// round 4
// speedup vs baseline: 2.1325x; 2.1325x over previous
#include <cuda_runtime.h>
#include <cstdint>

#define NN 100000
#define NE 1600000

typedef unsigned long long ull;

// Scratch (device globals — no runtime allocation allowed)
__device__ float g_SR[(size_t)NN * 256];  // [n][0:128]=nodes@W1a+b1, [128:256]=nodes@W1b
__device__ float g_deg[NN];               // degree, then 1/max(deg,1)

// ---------------------------------------------------------------------------
// packed fp32x2 helpers
// ---------------------------------------------------------------------------
__device__ __forceinline__ ull dup2(float x) {
    ull r; asm("mov.b64 %0,{%1,%1};" : "=l"(r) : "f"(x)); return r;
}
__device__ __forceinline__ float2 up2(ull v) {
    float2 r; asm("mov.b64 {%0,%1},%2;" : "=f"(r.x), "=f"(r.y) : "l"(v)); return r;
}
__device__ __forceinline__ ull pk2(float x, float y) {
    ull r; asm("mov.b64 %0,{%1,%2};" : "=l"(r) : "f"(x), "f"(y)); return r;
}
__device__ __forceinline__ ull fma2(ull a, ull b, ull c) {
    ull d; asm("fma.rn.f32x2 %0,%1,%2,%3;" : "=l"(d) : "l"(a), "l"(b), "l"(c)); return d;
}

// ---------------------------------------------------------------------------
// Degree kernels
// ---------------------------------------------------------------------------
__global__ void zero_deg_kernel() {
    int i = blockIdx.x * blockDim.x + threadIdx.x;
    if (i < NN) g_deg[i] = 0.0f;
}
__global__ void deg_kernel(const int* __restrict__ recv) {
    int e = blockIdx.x * blockDim.x + threadIdx.x;
    if (e < NE) atomicAdd(&g_deg[recv[e]], 1.0f);
}
__global__ void invdeg_kernel() {
    int i = blockIdx.x * blockDim.x + threadIdx.x;
    if (i < NN) g_deg[i] = 1.0f / fmaxf(g_deg[i], 1.0f);
}

// ---------------------------------------------------------------------------
// Fused S|R precompute: g_SR[M,256] = nodes[M,64] @ [W1a | W1b][64,256], b1 on S half
// ---------------------------------------------------------------------------
__global__ void __launch_bounds__(256) sr_gemm_kernel(
    const float* __restrict__ A,   // nodes [M,64]
    const float* __restrict__ W1,  // [160,128]
    const float* __restrict__ b1,  // [128]
    int M)
{
    extern __shared__ float sm[];
    float* sAT = sm;               // [64 k][68] transposed A tile
    float* sB  = sm + 64 * 68;     // [64 k][256 n]

    const int tid = threadIdx.x;
    const int n0  = blockIdx.x * 64;

#pragma unroll
    for (int j = 0; j < 4; j++) {
        int s   = tid + j * 256;
        int row = s >> 4;
        int k0  = (s & 15) << 2;
        int gn  = n0 + row;
        float4 v = make_float4(0.f, 0.f, 0.f, 0.f);
        if (gn < M) v = *(const float4*)(A + (size_t)gn * 64 + k0);
        sAT[(k0 + 0) * 68 + row] = v.x;
        sAT[(k0 + 1) * 68 + row] = v.y;
        sAT[(k0 + 2) * 68 + row] = v.z;
        sAT[(k0 + 3) * 68 + row] = v.w;
    }
#pragma unroll
    for (int j = 0; j < 16; j++) {
        int s  = tid + j * 256;
        int r  = s >> 6;
        int c4 = (s & 63) * 4;
        const float* src = (c4 < 128) ? (W1 + (size_t)r * 128 + c4)
                                      : (W1 + (size_t)(64 + r) * 128 + (c4 - 128));
        *(float4*)(sB + r * 256 + c4) = *(const float4*)src;
    }
    __syncthreads();

    const int ty = tid >> 4;
    const int tx = tid & 15;

    ull acc[4][4][2];
#pragma unroll
    for (int m = 0; m < 4; m++)
#pragma unroll
        for (int q = 0; q < 4; q++) { acc[m][q][0] = 0ull; acc[m][q][1] = 0ull; }

#pragma unroll 8
    for (int k = 0; k < 64; k++) {
        float4 a = *(const float4*)(sAT + k * 68 + ty * 4);
        ull aa[4] = {dup2(a.x), dup2(a.y), dup2(a.z), dup2(a.w)};
#pragma unroll
        for (int q = 0; q < 4; q++) {
            ulonglong2 b = *(const ulonglong2*)(sB + k * 256 + q * 64 + tx * 4);
#pragma unroll
            for (int m = 0; m < 4; m++) {
                acc[m][q][0] = fma2(aa[m], b.x, acc[m][q][0]);
                acc[m][q][1] = fma2(aa[m], b.y, acc[m][q][1]);
            }
        }
    }

    float4 bq[4];
#pragma unroll
    for (int q = 0; q < 4; q++) {
        if (q < 2) bq[q] = *(const float4*)(b1 + q * 64 + tx * 4);
        else       bq[q] = make_float4(0.f, 0.f, 0.f, 0.f);
    }

#pragma unroll
    for (int m = 0; m < 4; m++) {
        int gn = n0 + ty * 4 + m;
        if (gn < M) {
#pragma unroll
            for (int q = 0; q < 4; q++) {
                float2 u0 = up2(acc[m][q][0]);
                float2 u1 = up2(acc[m][q][1]);
                float4 v = make_float4(u0.x + bq[q].x, u0.y + bq[q].y,
                                       u1.x + bq[q].z, u1.y + bq[q].w);
                *(float4*)(g_SR + (size_t)gn * 256 + q * 64 + tx * 4) = v;
            }
        }
    }
}

// ---------------------------------------------------------------------------
// Node residual GEMM: out[M,64] = nodes @ Wn + bn
// ---------------------------------------------------------------------------
__global__ void __launch_bounds__(256) node_gemm_small(
    const float* __restrict__ A, const float* __restrict__ B,
    const float* __restrict__ bias, float* __restrict__ C, int M)
{
    extern __shared__ float sm[];
    float* sAT = sm;
    float* sB  = sm + 64 * 68;

    const int tid = threadIdx.x;
    const int n0  = blockIdx.x * 64;

#pragma unroll
    for (int j = 0; j < 4; j++) {
        int s   = tid + j * 256;
        int row = s >> 4;
        int k0  = (s & 15) << 2;
        int gn  = n0 + row;
        float4 v = make_float4(0.f, 0.f, 0.f, 0.f);
        if (gn < M) v = *(const float4*)(A + (size_t)gn * 64 + k0);
        sAT[(k0 + 0) * 68 + row] = v.x;
        sAT[(k0 + 1) * 68 + row] = v.y;
        sAT[(k0 + 2) * 68 + row] = v.z;
        sAT[(k0 + 3) * 68 + row] = v.w;
    }
#pragma unroll
    for (int j = 0; j < 4; j++) {
        int s = tid + j * 256;
        ((float4*)sB)[s] = ((const float4*)B)[s];
    }
    __syncthreads();

    const int ty = tid >> 4, tx = tid & 15;
    ull acc[4][2];
#pragma unroll
    for (int m = 0; m < 4; m++) { acc[m][0] = 0ull; acc[m][1] = 0ull; }

#pragma unroll 8
    for (int k = 0; k < 64; k++) {
        float4 a = *(const float4*)(sAT + k * 68 + ty * 4);
        ulonglong2 b = *(const ulonglong2*)(sB + k * 64 + tx * 4);
        ull aa[4] = {dup2(a.x), dup2(a.y), dup2(a.z), dup2(a.w)};
#pragma unroll
        for (int m = 0; m < 4; m++) {
            acc[m][0] = fma2(aa[m], b.x, acc[m][0]);
            acc[m][1] = fma2(aa[m], b.y, acc[m][1]);
        }
    }

    float4 bb = *(const float4*)(bias + tx * 4);
#pragma unroll
    for (int m = 0; m < 4; m++) {
        int gn = n0 + ty * 4 + m;
        if (gn < M) {
            float2 u0 = up2(acc[m][0]);
            float2 u1 = up2(acc[m][1]);
            float4 v = make_float4(u0.x + bb.x, u0.y + bb.y, u1.x + bb.z, u1.y + bb.w);
            *(float4*)(C + (size_t)gn * 64 + tx * 4) = v;
        }
    }
}

// ---------------------------------------------------------------------------
// Fused edge kernel: 64 edges / block, 256 threads, 2 blocks/SM, k-packed f32x2
// smem layout (floats):
//   sW1c  [32][128]            @ 0      (4096)
//   sW2k  [32 kq][264]         @ 4096   (8448)  interleaved 4k-group layout
//   sE    [64 e][36]           @ 12544  (2304)
//   sH    [64 e][132]          @ 14848  (8448)
//   sSend/sRecv [64]+[64] ints @ 23296
// total = 23424 floats = 93,696 B  -> 2 blocks/SM
// ---------------------------------------------------------------------------
__global__ void __launch_bounds__(256, 2) edge_kernel(
    const float* __restrict__ edges,       // [NE,32]
    const int*   __restrict__ senders,
    const int*   __restrict__ receivers,
    const float* __restrict__ W1,          // [160,128]
    const float* __restrict__ W2,          // [128,64]
    const float* __restrict__ b2,          // [64]
    float*       __restrict__ out)         // [NN,64]
{
    extern __shared__ float sm[];
    float* sW1c = sm;                      // 4096
    float* sW2k = sm + 4096;               // 8448
    float* sE   = sm + 12544;              // 2304
    float* sH   = sm + 14848;              // 8448
    int*   sSend = (int*)(sm + 23296);     // [64]
    int*   sRecv = sSend + 64;             // [64]

    const int tid = threadIdx.x;
    const int e0  = blockIdx.x * 64;

    if (tid < 64)               sSend[tid] = senders[e0 + tid];
    else if (tid < 128)         sRecv[tid - 64] = receivers[e0 + tid - 64];

    // W1 rows 128..159 -> sW1c (linear): 1024 float4 / 256 threads
#pragma unroll
    for (int j = 0; j < 4; j++) {
        int s = tid + j * 256;
        ((float4*)sW1c)[s] = ((const float4*)(W1 + 128 * 128))[s];
    }
    // W2 -> sW2k 4k-grouped: [(k>>2)*264 + (n&7)*32 + (n>>3)*4 + (k&3)]
#pragma unroll
    for (int j = 0; j < 32; j++) {
        int s = tid + j * 256;
        int k = s >> 6;
        int n = s & 63;
        sW2k[(k >> 2) * 264 + ((n & 7) << 5) + ((n >> 3) << 2) + (k & 3)] = W2[s];
    }
    // edges -> sE row-major [e][32]: 512 float4 / 256 threads
#pragma unroll
    for (int j = 0; j < 2; j++) {
        int s  = tid + j * 256;
        int e  = s >> 3;
        int i0 = (s & 7) * 4;
        *(float4*)(sE + e * 36 + i0) = *(const float4*)(edges + (size_t)(e0 + e) * 32 + i0);
    }
    __syncthreads();

    // ================= GEMM1: h[64e x 128k], pack along k =================
    {
        const int ty = tid >> 4;           // 0..15 -> edges ty*4..+3
        const int tx = tid & 15;           // 0..15 -> k cols tx*8..+7
        const int eb = ty * 4;
        const int kb = tx * 8;

        ull acc[4][4];
#pragma unroll
        for (int e = 0; e < 4; e++)
#pragma unroll
            for (int c = 0; c < 4; c++) acc[e][c] = 0ull;

#pragma unroll
        for (int i0 = 0; i0 < 32; i0 += 4) {
            float4 ev[4];
#pragma unroll
            for (int e = 0; e < 4; e++)
                ev[e] = *(const float4*)(sE + (eb + e) * 36 + i0);
#pragma unroll
            for (int ii = 0; ii < 4; ii++) {
                ulonglong2 w01 = *(const ulonglong2*)(sW1c + (i0 + ii) * 128 + kb);
                ulonglong2 w23 = *(const ulonglong2*)(sW1c + (i0 + ii) * 128 + kb + 4);
#pragma unroll
                for (int e = 0; e < 4; e++) {
                    float es = (ii == 0) ? ev[e].x : (ii == 1) ? ev[e].y
                             : (ii == 2) ? ev[e].z : ev[e].w;
                    ull aa = dup2(es);
                    acc[e][0] = fma2(aa, w01.x, acc[e][0]);
                    acc[e][1] = fma2(aa, w01.y, acc[e][1]);
                    acc[e][2] = fma2(aa, w23.x, acc[e][2]);
                    acc[e][3] = fma2(aa, w23.y, acc[e][3]);
                }
            }
        }

        // epilogue: h = relu(acc + S[send] + R[recv]); store [e][k] row-major
#pragma unroll
        for (int e = 0; e < 4; e++) {
            int ge = eb + e;
            int es = sSend[ge];
            int er = sRecv[ge];
            const float* Sp = g_SR + (size_t)es * 256 + kb;
            const float* Rp = g_SR + (size_t)er * 256 + 128 + kb;
            float4 s0 = *(const float4*)(Sp);
            float4 s1 = *(const float4*)(Sp + 4);
            float4 r0 = *(const float4*)(Rp);
            float4 r1 = *(const float4*)(Rp + 4);
            float2 u;
            u = up2(acc[e][0]);
            ull p0 = pk2(fmaxf(u.x + s0.x + r0.x, 0.f), fmaxf(u.y + s0.y + r0.y, 0.f));
            u = up2(acc[e][1]);
            ull p1 = pk2(fmaxf(u.x + s0.z + r0.z, 0.f), fmaxf(u.y + s0.w + r0.w, 0.f));
            u = up2(acc[e][2]);
            ull p2 = pk2(fmaxf(u.x + s1.x + r1.x, 0.f), fmaxf(u.y + s1.y + r1.y, 0.f));
            u = up2(acc[e][3]);
            ull p3 = pk2(fmaxf(u.x + s1.z + r1.z, 0.f), fmaxf(u.y + s1.w + r1.w, 0.f));
            ulonglong2* dst = (ulonglong2*)(sH + ge * 132 + kb);
            dst[0] = make_ulonglong2(p0, p1);
            dst[1] = make_ulonglong2(p2, p3);
        }
    }
    __syncthreads();

    // ========== GEMM2: m[64e x 64n] = h @ W2, both operands k-packed ==========
    {
        const int ty2 = tid >> 3;          // 0..31 -> edges ty2*2..+1
        const int tx2 = tid & 7;           // 0..7  -> n cols tx2*8..+7
        const int eb2 = ty2 * 2;
        const int nb  = tx2 * 8;

        const float* h0 = sH + (eb2 + 0) * 132;
        const float* h1 = sH + (eb2 + 1) * 132;

        ull acc2[2][8];
#pragma unroll
        for (int e = 0; e < 2; e++)
#pragma unroll
            for (int j = 0; j < 8; j++) acc2[e][j] = 0ull;

#pragma unroll 4
        for (int q = 0; q < 32; q++) {     // k-quad: k = 4q..4q+3
            ulonglong2 ha = *(const ulonglong2*)(h0 + q * 4);
            ulonglong2 hb = *(const ulonglong2*)(h1 + q * 4);
            const float* wrow = sW2k + q * 264 + (tx2 << 2);
#pragma unroll
            for (int j = 0; j < 8; j++) {
                ulonglong2 w = *(const ulonglong2*)(wrow + (j << 5));
                acc2[0][j] = fma2(ha.x, w.x, acc2[0][j]);
                acc2[0][j] = fma2(ha.y, w.y, acc2[0][j]);
                acc2[1][j] = fma2(hb.x, w.x, acc2[1][j]);
                acc2[1][j] = fma2(hb.y, w.y, acc2[1][j]);
            }
        }

        // epilogue 2: m = hadd(acc2) + b2, scale by invdeg, vector-red scatter
        float4 b2a = *(const float4*)(b2 + nb);
        float4 b2b = *(const float4*)(b2 + nb + 4);
        float bnv[8] = {b2a.x, b2a.y, b2a.z, b2a.w, b2b.x, b2b.y, b2b.z, b2b.w};

#pragma unroll
        for (int e = 0; e < 2; e++) {
            int er = sRecv[eb2 + e];
            float invd = g_deg[er];
            float mv[8];
#pragma unroll
            for (int j = 0; j < 8; j++) {
                float2 u = up2(acc2[e][j]);
                mv[j] = (u.x + u.y + bnv[j]) * invd;
            }
            float* p = out + (size_t)er * 64 + nb;
            asm volatile("red.global.add.v4.f32 [%0], {%1,%2,%3,%4};"
                         :: "l"(p), "f"(mv[0]), "f"(mv[1]), "f"(mv[2]), "f"(mv[3]) : "memory");
            asm volatile("red.global.add.v4.f32 [%0], {%1,%2,%3,%4};"
                         :: "l"(p + 4), "f"(mv[4]), "f"(mv[5]), "f"(mv[6]), "f"(mv[7]) : "memory");
        }
    }
}

// ---------------------------------------------------------------------------
// Launch
// ---------------------------------------------------------------------------
extern "C" void kernel_launch(void* const* d_in, const int* in_sizes, int n_in,
                              void* d_out, int out_size)
{
    const float* nodes     = (const float*)d_in[0];
    const float* edges     = (const float*)d_in[1];
    const int*   senders   = (const int*)d_in[2];
    const int*   receivers = (const int*)d_in[3];
    const float* W1        = (const float*)d_in[4];
    const float* b1        = (const float*)d_in[5];
    const float* W2        = (const float*)d_in[6];
    const float* b2        = (const float*)d_in[7];
    const float* Wn        = (const float*)d_in[8];
    const float* bn        = (const float*)d_in[9];
    float* out = (float*)d_out;

    const size_t sm_sr    = (64 * 68 + 64 * 256) * sizeof(float);
    const size_t sm_small = (64 * 68 + 64 * 64) * sizeof(float);
    const size_t sm_edge  = (23296 + 128) * sizeof(float);   // 93,696 B

    cudaFuncSetAttribute(sr_gemm_kernel,
                         cudaFuncAttributeMaxDynamicSharedMemorySize, (int)sm_sr);
    cudaFuncSetAttribute(edge_kernel,
                         cudaFuncAttributeMaxDynamicSharedMemorySize, (int)sm_edge);

    zero_deg_kernel<<<(NN + 255) / 256, 256>>>();
    deg_kernel<<<(NE + 255) / 256, 256>>>(receivers);
    invdeg_kernel<<<(NN + 255) / 256, 256>>>();

    int gnodes = (NN + 63) / 64;
    sr_gemm_kernel<<<gnodes, 256, sm_sr>>>(nodes, W1, b1, NN);
    node_gemm_small<<<gnodes, 256, sm_small>>>(nodes, Wn, bn, out, NN);

    edge_kernel<<<NE / 64, 256, sm_edge>>>(edges, senders, receivers, W1, W2, b2, out);
}

// round 7
// speedup vs baseline: 4.0382x; 1.8936x over previous
#include <cuda_runtime.h>
#include <cuda_bf16.h>
#include <cstdint>

#define NN 100000
#define NE 1600000

typedef unsigned long long ull;

// ---------------------------------------------------------------------------
// Device scratch (no runtime allocation allowed)
// ---------------------------------------------------------------------------
__device__ float g_SR[(size_t)NN * 256];   // [n][0:128]=S(+b1), [128:256]=R
__device__ float g_deg[NN];                // 1/max(deg,1) after invdeg
__device__ ull   g_W1f[16 * 2 * 2 * 32];   // B1 frags: [j16][t2][term2][lane32]
__device__ ull   g_W2f[8 * 8 * 2 * 32];    // B2 frags: [j8][t8][term2][lane32]

// ---------------------------------------------------------------------------
// helpers
// ---------------------------------------------------------------------------
__device__ __forceinline__ void mma16816(float c[4], const uint32_t a[4],
                                         uint32_t b0, uint32_t b1) {
    asm volatile(
        "mma.sync.aligned.m16n8k16.row.col.f32.bf16.bf16.f32 "
        "{%0,%1,%2,%3},{%4,%5,%6,%7},{%8,%9},{%0,%1,%2,%3};"
        : "+f"(c[0]), "+f"(c[1]), "+f"(c[2]), "+f"(c[3])
        : "r"(a[0]), "r"(a[1]), "r"(a[2]), "r"(a[3]), "r"(b0), "r"(b1));
}

// pack (x -> low half, y -> high half) as bf16x2; also produce residual pack
__device__ __forceinline__ void bfs2(float x, float y, uint32_t& hi, uint32_t& lo) {
    asm("cvt.rn.bf16x2.f32 %0, %1, %2;" : "=r"(hi) : "f"(y), "f"(x));
    float xr = x - __uint_as_float(hi << 16);
    float yr = y - __uint_as_float(hi & 0xFFFF0000u);
    asm("cvt.rn.bf16x2.f32 %0, %1, %2;" : "=r"(lo) : "f"(yr), "f"(xr));
}

// fp32x2 helpers for node-side kernels
__device__ __forceinline__ ull dup2(float x) { ull r; asm("mov.b64 %0,{%1,%1};" : "=l"(r) : "f"(x)); return r; }
__device__ __forceinline__ float2 up2(ull v) { float2 r; asm("mov.b64 {%0,%1},%2;" : "=f"(r.x), "=f"(r.y) : "l"(v)); return r; }
__device__ __forceinline__ ull fma2(ull a, ull b, ull c) { ull d; asm("fma.rn.f32x2 %0,%1,%2,%3;" : "=l"(d) : "l"(a), "l"(b), "l"(c)); return d; }

// ---------------------------------------------------------------------------
// Degree kernels
// ---------------------------------------------------------------------------
__global__ void zero_deg_kernel() {
    int i = blockIdx.x * blockDim.x + threadIdx.x;
    if (i < NN) g_deg[i] = 0.0f;
}
__global__ void deg_kernel(const int* __restrict__ recv) {
    int e = blockIdx.x * blockDim.x + threadIdx.x;
    if (e < NE) atomicAdd(&g_deg[recv[e]], 1.0f);
}
__global__ void invdeg_kernel() {
    int i = blockIdx.x * blockDim.x + threadIdx.x;
    if (i < NN) g_deg[i] = 1.0f / fmaxf(g_deg[i], 1.0f);
}

// ---------------------------------------------------------------------------
// Weight fragment prep: bake W1c (rows 128..159 of W1) and W2 into
// mma.sync B-fragment order, bf16 hi/lo split.
// B frag (m16n8k16, col-major): lane -> n = j*8 + (lane>>2), k0 = t*16 + (lane&3)*2
//   reg0 = {v(k0), v(k0+1)}, reg1 = {v(k0+8), v(k0+9)}; ull = (reg1<<32)|reg0
// ---------------------------------------------------------------------------
__global__ void prep_frags(const float* __restrict__ W1, const float* __restrict__ W2) {
    int idx = blockIdx.x * blockDim.x + threadIdx.x;
    if (idx < 2048) {                        // W1 frags: 64 frags x 32 lanes
        int lane = idx & 31, fragid = idx >> 5;
        int term = fragid & 1, t = (fragid >> 1) & 1, j = fragid >> 2;
        int n = j * 8 + (lane >> 2);
        int k0 = t * 16 + (lane & 3) * 2;
        float v00 = W1[(size_t)(128 + k0) * 128 + n];
        float v01 = W1[(size_t)(128 + k0 + 1) * 128 + n];
        float v10 = W1[(size_t)(128 + k0 + 8) * 128 + n];
        float v11 = W1[(size_t)(128 + k0 + 9) * 128 + n];
        uint32_t h0, l0, h1, l1;
        bfs2(v00, v01, h0, l0);
        bfs2(v10, v11, h1, l1);
        ull fr = term ? (((ull)l1 << 32) | l0) : (((ull)h1 << 32) | h0);
        g_W1f[idx] = fr;
    }
    if (idx < 4096) {                        // W2 frags: 128 frags x 32 lanes
        int lane = idx & 31, fragid = idx >> 5;
        int term = fragid & 1, t = (fragid >> 1) & 7, j = fragid >> 4;
        int n = j * 8 + (lane >> 2);
        int k0 = t * 16 + (lane & 3) * 2;
        float v00 = W2[(size_t)k0 * 64 + n];
        float v01 = W2[(size_t)(k0 + 1) * 64 + n];
        float v10 = W2[(size_t)(k0 + 8) * 64 + n];
        float v11 = W2[(size_t)(k0 + 9) * 64 + n];
        uint32_t h0, l0, h1, l1;
        bfs2(v00, v01, h0, l0);
        bfs2(v10, v11, h1, l1);
        ull fr = term ? (((ull)l1 << 32) | l0) : (((ull)h1 << 32) | h0);
        g_W2f[idx] = fr;
    }
}

// ---------------------------------------------------------------------------
// Fused S|R precompute (proven): g_SR = nodes @ [W1a|W1b] (+b1 on S half)
// ---------------------------------------------------------------------------
__global__ void __launch_bounds__(256) sr_gemm_kernel(
    const float* __restrict__ A, const float* __restrict__ W1,
    const float* __restrict__ b1, int M)
{
    extern __shared__ float sm[];
    float* sAT = sm;               // [64][68]
    float* sB  = sm + 64 * 68;     // [64][256]
    const int tid = threadIdx.x;
    const int n0  = blockIdx.x * 64;

#pragma unroll
    for (int j = 0; j < 4; j++) {
        int s = tid + j * 256;
        int row = s >> 4, k0 = (s & 15) << 2, gn = n0 + row;
        float4 v = make_float4(0.f, 0.f, 0.f, 0.f);
        if (gn < M) v = *(const float4*)(A + (size_t)gn * 64 + k0);
        sAT[(k0 + 0) * 68 + row] = v.x; sAT[(k0 + 1) * 68 + row] = v.y;
        sAT[(k0 + 2) * 68 + row] = v.z; sAT[(k0 + 3) * 68 + row] = v.w;
    }
#pragma unroll
    for (int j = 0; j < 16; j++) {
        int s = tid + j * 256;
        int r = s >> 6, c4 = (s & 63) * 4;
        const float* src = (c4 < 128) ? (W1 + (size_t)r * 128 + c4)
                                      : (W1 + (size_t)(64 + r) * 128 + (c4 - 128));
        *(float4*)(sB + r * 256 + c4) = *(const float4*)src;
    }
    __syncthreads();

    const int ty = tid >> 4, tx = tid & 15;
    ull acc[4][4][2];
#pragma unroll
    for (int m = 0; m < 4; m++)
#pragma unroll
        for (int q = 0; q < 4; q++) { acc[m][q][0] = 0ull; acc[m][q][1] = 0ull; }

#pragma unroll 8
    for (int k = 0; k < 64; k++) {
        float4 a = *(const float4*)(sAT + k * 68 + ty * 4);
        ull aa[4] = {dup2(a.x), dup2(a.y), dup2(a.z), dup2(a.w)};
#pragma unroll
        for (int q = 0; q < 4; q++) {
            ulonglong2 b = *(const ulonglong2*)(sB + k * 256 + q * 64 + tx * 4);
#pragma unroll
            for (int m = 0; m < 4; m++) {
                acc[m][q][0] = fma2(aa[m], b.x, acc[m][q][0]);
                acc[m][q][1] = fma2(aa[m], b.y, acc[m][q][1]);
            }
        }
    }
    float4 bq[4];
#pragma unroll
    for (int q = 0; q < 4; q++)
        bq[q] = (q < 2) ? *(const float4*)(b1 + q * 64 + tx * 4)
                        : make_float4(0.f, 0.f, 0.f, 0.f);
#pragma unroll
    for (int m = 0; m < 4; m++) {
        int gn = n0 + ty * 4 + m;
        if (gn < M) {
#pragma unroll
            for (int q = 0; q < 4; q++) {
                float2 u0 = up2(acc[m][q][0]), u1 = up2(acc[m][q][1]);
                *(float4*)(g_SR + (size_t)gn * 256 + q * 64 + tx * 4) =
                    make_float4(u0.x + bq[q].x, u0.y + bq[q].y, u1.x + bq[q].z, u1.y + bq[q].w);
            }
        }
    }
}

// ---------------------------------------------------------------------------
// Node residual GEMM: out = nodes @ Wn + bn
// ---------------------------------------------------------------------------
__global__ void __launch_bounds__(256) node_gemm_small(
    const float* __restrict__ A, const float* __restrict__ B,
    const float* __restrict__ bias, float* __restrict__ C, int M)
{
    extern __shared__ float sm[];
    float* sAT = sm;
    float* sB  = sm + 64 * 68;
    const int tid = threadIdx.x;
    const int n0  = blockIdx.x * 64;

#pragma unroll
    for (int j = 0; j < 4; j++) {
        int s = tid + j * 256;
        int row = s >> 4, k0 = (s & 15) << 2, gn = n0 + row;
        float4 v = make_float4(0.f, 0.f, 0.f, 0.f);
        if (gn < M) v = *(const float4*)(A + (size_t)gn * 64 + k0);
        sAT[(k0 + 0) * 68 + row] = v.x; sAT[(k0 + 1) * 68 + row] = v.y;
        sAT[(k0 + 2) * 68 + row] = v.z; sAT[(k0 + 3) * 68 + row] = v.w;
    }
#pragma unroll
    for (int j = 0; j < 4; j++) {
        int s = tid + j * 256;
        ((float4*)sB)[s] = ((const float4*)B)[s];
    }
    __syncthreads();

    const int ty = tid >> 4, tx = tid & 15;
    ull acc[4][2];
#pragma unroll
    for (int m = 0; m < 4; m++) { acc[m][0] = 0ull; acc[m][1] = 0ull; }
#pragma unroll 8
    for (int k = 0; k < 64; k++) {
        float4 a = *(const float4*)(sAT + k * 68 + ty * 4);
        ulonglong2 b = *(const ulonglong2*)(sB + k * 64 + tx * 4);
        ull aa[4] = {dup2(a.x), dup2(a.y), dup2(a.z), dup2(a.w)};
#pragma unroll
        for (int m = 0; m < 4; m++) {
            acc[m][0] = fma2(aa[m], b.x, acc[m][0]);
            acc[m][1] = fma2(aa[m], b.y, acc[m][1]);
        }
    }
    float4 bb = *(const float4*)(bias + tx * 4);
#pragma unroll
    for (int m = 0; m < 4; m++) {
        int gn = n0 + ty * 4 + m;
        if (gn < M) {
            float2 u0 = up2(acc[m][0]), u1 = up2(acc[m][1]);
            *(float4*)(C + (size_t)gn * 64 + tx * 4) =
                make_float4(u0.x + bb.x, u0.y + bb.y, u1.x + bb.z, u1.y + bb.w);
        }
    }
}

// ---------------------------------------------------------------------------
// Edge kernel: persistent warps, mma.sync bf16x3, register-resident fusion.
// Each warp owns independent 32-edge chunks (2 m-tiles of 16).
// smem: W1 frags 16KB @0, W2 frags 32KB @16384, edges [4 warps][32][36] @49152
// ---------------------------------------------------------------------------
#define N_CHUNKS (NE / 32)

__global__ void __launch_bounds__(128, 2) edge_kernel(
    const float* __restrict__ edges,
    const int*   __restrict__ senders,
    const int*   __restrict__ receivers,
    const float* __restrict__ b2,
    float*       __restrict__ out)
{
    extern __shared__ char smem[];
    ull*   sW1f = (ull*)smem;
    ull*   sW2f = (ull*)(smem + 16384);
    float* sE   = (float*)(smem + 49152);

    const int tid  = threadIdx.x;
    const int w    = tid >> 5;
    const int lane = tid & 31;

    // stage weight fragments once
#pragma unroll
    for (int j = 0; j < 16; j++) sW1f[tid + j * 128] = g_W1f[tid + j * 128];
#pragma unroll
    for (int j = 0; j < 32; j++) sW2f[tid + j * 128] = g_W2f[tid + j * 128];
    __syncthreads();

    float* myE = sE + w * 32 * 36;
    const int gw     = blockIdx.x * 4 + w;
    const int stride = gridDim.x * 4;

    const int r   = lane >> 2;          // 0..7
    const int c2x = (lane & 3) * 2;     // 0,2,4,6
    const int pb  = (lane >> 1) & 1;    // pair base selector
    const bool oddl = lane & 1;

    for (int chunk = gw; chunk < N_CHUNKS; chunk += stride) {
        const int e0 = chunk * 32;
        __syncwarp();
        // stage this warp's 32 edge rows (coalesced), pitch 36
#pragma unroll
        for (int q = 0; q < 8; q++) {
            int row = q * 4 + (lane >> 3);
            int col = (lane & 7) * 4;
            *(float4*)(myE + row * 36 + col) =
                *(const float4*)(edges + (size_t)(e0 + row) * 32 + col);
        }
        const int snd = senders[e0 + lane];
        const int rcv = receivers[e0 + lane];
        const float ivl = g_deg[rcv];
        __syncwarp();

#pragma unroll
        for (int mt = 0; mt < 2; mt++) {
            const int mb = mt * 16;

            // ---- A1 fragments (edge feats, hi/lo split), k-steps t=0,1 ----
            uint32_t a1h[2][4], a1l[2][4];
#pragma unroll
            for (int t = 0; t < 2; t++) {
                float2 x0 = *(const float2*)(myE + (mb + r) * 36 + t * 16 + c2x);
                float2 x1 = *(const float2*)(myE + (mb + r + 8) * 36 + t * 16 + c2x);
                float2 x2 = *(const float2*)(myE + (mb + r) * 36 + t * 16 + c2x + 8);
                float2 x3 = *(const float2*)(myE + (mb + r + 8) * 36 + t * 16 + c2x + 8);
                bfs2(x0.x, x0.y, a1h[t][0], a1l[t][0]);
                bfs2(x1.x, x1.y, a1h[t][1], a1l[t][1]);
                bfs2(x2.x, x2.y, a1h[t][2], a1l[t][2]);
                bfs2(x3.x, x3.y, a1h[t][3], a1l[t][3]);
            }

            // gather bases for this m-tile
            const int s_r  = __shfl_sync(0xFFFFFFFFu, snd, mb + r);
            const int s_r8 = __shfl_sync(0xFFFFFFFFu, snd, mb + r + 8);
            const int r_r  = __shfl_sync(0xFFFFFFFFu, rcv, mb + r);
            const int r_r8 = __shfl_sync(0xFFFFFFFFu, rcv, mb + r + 8);
            const float* Sr  = g_SR + (size_t)s_r  * 256;
            const float* Sr8 = g_SR + (size_t)s_r8 * 256;
            const float* Rr  = g_SR + (size_t)r_r  * 256 + 128;
            const float* Rr8 = g_SR + (size_t)r_r8 * 256 + 128;

            // ---- GEMM1 (pairs of n-tiles) + epilogue1 -> A2 frags ----
            uint32_t a2h[8][4], a2l[8][4];
#pragma unroll
            for (int t2 = 0; t2 < 8; t2++) {
                float c1[2][4] = {{0.f, 0.f, 0.f, 0.f}, {0.f, 0.f, 0.f, 0.f}};
#pragma unroll
                for (int half = 0; half < 2; half++) {
                    int j = t2 * 2 + half;
#pragma unroll
                    for (int t = 0; t < 1 + 1; t++) {
                        ull bh = sW1f[((j * 2 + t) * 2 + 0) * 32 + lane];
                        ull bl = sW1f[((j * 2 + t) * 2 + 1) * 32 + lane];
                        uint32_t bh0 = (uint32_t)bh, bh1 = (uint32_t)(bh >> 32);
                        uint32_t bl0 = (uint32_t)bl, bl1 = (uint32_t)(bl >> 32);
                        mma16816(c1[half], a1h[t], bh0, bh1);
                        mma16816(c1[half], a1h[t], bl0, bl1);
                        mma16816(c1[half], a1l[t], bh0, bh1);
                    }
                }
                // epilogue: h = relu(c1 + S + R), split -> A2[t2]
#pragma unroll
                for (int half = 0; half < 2; half++) {
                    int j = t2 * 2 + half;
                    float2 sv0 = *(const float2*)(Sr  + j * 8 + c2x);
                    float2 sv1 = *(const float2*)(Sr8 + j * 8 + c2x);
                    float2 rv0 = *(const float2*)(Rr  + j * 8 + c2x);
                    float2 rv1 = *(const float2*)(Rr8 + j * 8 + c2x);
                    float h0 = fmaxf(c1[half][0] + sv0.x + rv0.x, 0.f);
                    float h1 = fmaxf(c1[half][1] + sv0.y + rv0.y, 0.f);
                    float h2 = fmaxf(c1[half][2] + sv1.x + rv1.x, 0.f);
                    float h3 = fmaxf(c1[half][3] + sv1.y + rv1.y, 0.f);
                    bfs2(h0, h1, a2h[t2][half * 2 + 0], a2l[t2][half * 2 + 0]);
                    bfs2(h2, h3, a2h[t2][half * 2 + 1], a2l[t2][half * 2 + 1]);
                }
            }

            // scatter metadata
            const float iv_e = __shfl_sync(0xFFFFFFFFu, ivl, mb + r);
            const float iv_o = __shfl_sync(0xFFFFFFFFu, ivl, mb + r + 8);
            const int   er   = oddl ? r_r8 : r_r;
            const float iv   = oddl ? iv_o : iv_e;
            float* outp = out + (size_t)er * 64 + pb * 4;

            // ---- GEMM2 per n-tile + epilogue2 scatter ----
#pragma unroll
            for (int j = 0; j < 8; j++) {
                float c2[4] = {0.f, 0.f, 0.f, 0.f};
#pragma unroll
                for (int t = 0; t < 8; t++) {
                    ull bh = sW2f[((j * 8 + t) * 2 + 0) * 32 + lane];
                    ull bl = sW2f[((j * 8 + t) * 2 + 1) * 32 + lane];
                    uint32_t bh0 = (uint32_t)bh, bh1 = (uint32_t)(bh >> 32);
                    uint32_t bl0 = (uint32_t)bl, bl1 = (uint32_t)(bl >> 32);
                    mma16816(c2, a2h[t], bh0, bh1);
                    mma16816(c2, a2h[t], bl0, bl1);
                    mma16816(c2, a2l[t], bh0, bh1);
                }
                // lane-pair exchange: even lane -> row r (4 cols), odd -> row r+8
                float x0 = __shfl_xor_sync(0xFFFFFFFFu, c2[0], 1);
                float x1 = __shfl_xor_sync(0xFFFFFFFFu, c2[1], 1);
                float x2 = __shfl_xor_sync(0xFFFFFFFFu, c2[2], 1);
                float x3 = __shfl_xor_sync(0xFFFFFFFFu, c2[3], 1);
                float v0, v1, v2, v3;
                if (!oddl) { v0 = c2[0]; v1 = c2[1]; v2 = x0; v3 = x1; }
                else       { v0 = x2;    v1 = x3;    v2 = c2[2]; v3 = c2[3]; }
                float4 bb = *(const float4*)(b2 + j * 8 + pb * 4);
                v0 = (v0 + bb.x) * iv;  v1 = (v1 + bb.y) * iv;
                v2 = (v2 + bb.z) * iv;  v3 = (v3 + bb.w) * iv;
                asm volatile("red.global.add.v4.f32 [%0], {%1,%2,%3,%4};"
                             :: "l"(outp + j * 8), "f"(v0), "f"(v1), "f"(v2), "f"(v3)
                             : "memory");
            }
        }
    }
}

// ---------------------------------------------------------------------------
// Launch
// ---------------------------------------------------------------------------
extern "C" void kernel_launch(void* const* d_in, const int* in_sizes, int n_in,
                              void* d_out, int out_size)
{
    const float* nodes     = (const float*)d_in[0];
    const float* edges     = (const float*)d_in[1];
    const int*   senders   = (const int*)d_in[2];
    const int*   receivers = (const int*)d_in[3];
    const float* W1        = (const float*)d_in[4];
    const float* b1        = (const float*)d_in[5];
    const float* W2        = (const float*)d_in[6];
    const float* b2        = (const float*)d_in[7];
    const float* Wn        = (const float*)d_in[8];
    const float* bn        = (const float*)d_in[9];
    float* out = (float*)d_out;

    const size_t sm_sr    = (64 * 68 + 64 * 256) * sizeof(float);
    const size_t sm_small = (64 * 68 + 64 * 64) * sizeof(float);
    const size_t sm_edge  = 16384 + 32768 + 4 * 32 * 36 * sizeof(float);  // 67,584

    cudaFuncSetAttribute(sr_gemm_kernel,
                         cudaFuncAttributeMaxDynamicSharedMemorySize, (int)sm_sr);
    cudaFuncSetAttribute(edge_kernel,
                         cudaFuncAttributeMaxDynamicSharedMemorySize, (int)sm_edge);

    zero_deg_kernel<<<(NN + 255) / 256, 256>>>();
    deg_kernel<<<(NE + 255) / 256, 256>>>(receivers);
    invdeg_kernel<<<(NN + 255) / 256, 256>>>();

    prep_frags<<<16, 256>>>(W1, W2);

    int gnodes = (NN + 63) / 64;
    sr_gemm_kernel<<<gnodes, 256, sm_sr>>>(nodes, W1, b1, NN);
    node_gemm_small<<<gnodes, 256, sm_small>>>(nodes, Wn, bn, out, NN);

    edge_kernel<<<304, 128, sm_edge>>>(edges, senders, receivers, b2, out);
}